// round 17
// baseline (speedup 1.0000x reference)
#include <cuda_runtime.h>
#include <math.h>

#define FRAME_LEN 400
#define HOP 160
#define FFT_LEN 512
#define NBINS 257
#define NMEL 80
#define PREEMPH 0.97f
#define MEL_FLOOR 1.192092955078125e-07f
#define ABLOCKS 592
#define WCAP 640
#define PB 512               // per-block stat slots: 4 groups x 2 slots x 64

// ---- device scratch ----
#define MAX_FRAMES 60000
__device__ float  g_mel [MAX_FRAMES * NMEL];
__device__ float2 g_twid[512];
__device__ float  g_psum[ABLOCKS * PB];
__device__ float  g_psq [ABLOCKS * PB];
__device__ float  g_mean[NMEL];
__device__ float  g_istd[NMEL];
__device__ int    g_klo[NMEL];
__device__ int    g_wid[NMEL];
__device__ int    g_off[NMEL];
__device__ float  g_wts[WCAP];

// ---------------------------------------------------------------------------
// init (640 threads): twiddles + parallel filterbank compaction (8 lanes/bin).
// Weight offsets parity-matched to k_lo so mel uses float2 loads on both
// spec and weights simultaneously.
__global__ void init_kernel(const float* __restrict__ fb) {
    __shared__ int lo_sh[NMEL], wid_sh[NMEL], off_sh[NMEL];
    const int tid = threadIdx.x;

    if (tid < 512) {
        double a = -2.0 * 3.14159265358979323846 * (double)tid / 512.0;
        g_twid[tid] = make_float2((float)cos(a), (float)sin(a));
    }

    const int b = tid >> 3;      // 0..79
    const int s = tid & 7;
    int lo = 512, hi = -1;
    for (int k = s; k < NBINS; k += 8) {
        if (fb[k * NMEL + b] != 0.0f) { lo = min(lo, k); hi = max(hi, k); }
    }
    #pragma unroll
    for (int o = 4; o > 0; o >>= 1) {
        lo = min(lo, __shfl_xor_sync(0xffffffffu, lo, o));
        hi = max(hi, __shfl_xor_sync(0xffffffffu, hi, o));
    }
    if (s == 0) {
        lo_sh[b]  = (hi >= lo) ? lo : 0;
        wid_sh[b] = (hi >= lo) ? (hi - lo + 1) : 0;
    }
    __syncthreads();
    if (tid == 0) {
        int off = 0;
        for (int i = 0; i < NMEL; ++i) {
            if ((off ^ lo_sh[i]) & 1) off += 1;    // parity-match off to lo
            int w = wid_sh[i];
            if (off + w > WCAP) w = WCAP - off;
            if (w < 0) w = 0;
            wid_sh[i] = w;
            off_sh[i] = off;
            off += w;
        }
    }
    __syncthreads();
    if (tid < NMEL) {
        g_klo[tid] = lo_sh[tid];
        g_wid[tid] = wid_sh[tid];
        g_off[tid] = off_sh[tid];
    }
    {
        int off = off_sh[b], l0 = lo_sh[b], w = wid_sh[b];
        for (int i = s; i < w; i += 8)
            g_wts[off + i] = fb[(l0 + i) * NMEL + b];
    }
}

// ---------------------------------------------------------------------------
#define PHYS8(i) ((i) + ((i) >> 3))
#define BUF 576                 // float2 elems per group buffer
#define SPEC_LD 272             // even: preserves k parity across frames

#define FFT2(ar,ai,br,bi) { float tr_=ar, ti_=ai; ar=tr_+br; ai=ti_+bi; br=tr_-br; bi=ti_-bi; }
#define CMUL(xr,xi,wr,wi) { float tr_=xr; xr=tr_*(wr)-xi*(wi); xi=tr_*(wi)+xi*(wr); }
#define RSQ2 0.70710678118654752440f
#define GBAR() asm volatile("bar.sync %0, 64;" :: "r"(1 + g) : "memory")

__device__ __forceinline__ void fft8(float* vr, float* vi) {
    FFT2(vr[0], vi[0], vr[4], vi[4]);
    FFT2(vr[1], vi[1], vr[5], vi[5]);
    FFT2(vr[2], vi[2], vr[6], vi[6]);
    FFT2(vr[3], vi[3], vr[7], vi[7]);
    CMUL(vr[5], vi[5],  RSQ2, -RSQ2);
    CMUL(vr[6], vi[6],  0.0f, -1.0f);
    CMUL(vr[7], vi[7], -RSQ2, -RSQ2);
    FFT2(vr[0], vi[0], vr[2], vi[2]);
    FFT2(vr[1], vi[1], vr[3], vi[3]);
    FFT2(vr[4], vi[4], vr[6], vi[6]);
    FFT2(vr[5], vi[5], vr[7], vi[7]);
    CMUL(vr[3], vi[3], 0.0f, -1.0f);
    CMUL(vr[7], vi[7], 0.0f, -1.0f);
    FFT2(vr[0], vi[0], vr[1], vi[1]);
    FFT2(vr[2], vi[2], vr[3], vi[3]);
    FFT2(vr[4], vi[4], vr[5], vi[5]);
    FFT2(vr[6], vi[6], vr[7], vi[7]);
}

__global__ __launch_bounds__(256, 4)
void fused_kernel(const float* __restrict__ wav,
                  const float* __restrict__ window,
                  int num_frames, int T) {
    extern __shared__ __align__(16) char dyn[];
    float2 (*A)[BUF] = (float2(*)[BUF])dyn;
    float2 (*B)[BUF] = (float2(*)[BUF])(dyn + 4 * BUF * 8);

    __shared__ __align__(8) float wts_s[WCAP];
    __shared__ float  msum[4][4];      // per-group mean partials
    __shared__ int    klo_s[NMEL], wid_s[NMEL], off_s[NMEL];

    const int tid  = threadIdx.x;
    const int g    = tid >> 6;      // independent 64-thread group
    const int j    = tid & 63;
    const int w    = j >> 5;        // warp within group
    const int lane = j & 31;

    float* specg = (float*)&A[g][0];

    // per-thread twiddle bases (fixed across iterations)
    const float2 b2 = g_twid[(j & 7) << 3];   // W512^{8q}
    const float2 b3 = g_twid[j];              // W512^{j}

    // window cached in registers at pass-1 positions n = j + 64r
    float win_r[7];
    #pragma unroll
    for (int r = 0; r < 7; ++r) {
        int n = j + 64 * r;
        win_r[r] = (n < FRAME_LEN) ? window[n] : 0.0f;
    }

    if (tid < NMEL) {
        klo_s[tid] = g_klo[tid];
        wid_s[tid] = g_wid[tid];
        off_s[tid] = g_off[tid];
    }
    __syncthreads();
    {
        int tot = off_s[NMEL - 1] + wid_s[NMEL - 1];
        for (int i = tid; i < tot; i += 256) wts_s[i] = g_wts[i];
    }
    __syncthreads();

    float acc_s[2] = {0.f, 0.f};
    float acc_q[2] = {0.f, 0.f};
    const int BRv[8] = {0, 4, 2, 6, 1, 5, 3, 7};

    for (int base = blockIdx.x * 8; base < num_frames; base += gridDim.x * 8) {
        const int fg = base + 2 * g;

        // ---- phase 1: load both packed frames at pass-1 positions n = j + 64r
        float a[7], bb[7], pa[7], pb[7];
        {
            const int fA = fg, fB = fg + 1;
            #pragma unroll
            for (int r = 0; r < 7; ++r) { a[r] = 0.f; bb[r] = 0.f; pa[r] = 0.f; pb[r] = 0.f; }
            if (fA < num_frames) {
                const float* p = wav + (long long)fA * HOP;
                #pragma unroll
                for (int r = 0; r < 6; ++r) {
                    int n = j + 64 * r;
                    a[r] = p[n];
                    if (n >= 1) pa[r] = p[n - 1];
                }
                if (j < 16) { a[6] = p[j + 384]; pa[6] = p[j + 383]; }
            }
            if (fB < num_frames) {
                const float* p = wav + (long long)fB * HOP;
                #pragma unroll
                for (int r = 0; r < 6; ++r) {
                    int n = j + 64 * r;
                    bb[r] = p[n];
                    if (n >= 1) pb[r] = p[n - 1];
                }
                if (j < 16) { bb[6] = p[j + 384]; pb[6] = p[j + 383]; }
            }
        }
        // frame sums
        {
            float sA = ((a[0] + a[1]) + (a[2] + a[3])) + ((a[4] + a[5]) + a[6]);
            float sB = ((bb[0] + bb[1]) + (bb[2] + bb[3])) + ((bb[4] + bb[5]) + bb[6]);
            #pragma unroll
            for (int o = 16; o > 0; o >>= 1) {
                sA += __shfl_xor_sync(0xffffffffu, sA, o);
                sB += __shfl_xor_sync(0xffffffffu, sB, o);
            }
            if (lane == 0) { msum[g][2 * w] = sA; msum[g][2 * w + 1] = sB; }
        }
        GBAR();   // mean exchange; also orders prev-iter mel A-reads / unpack B-reads

        float vr[8], vi[8];
        {
            const float mA  = (msum[g][0] + msum[g][2]) * (32768.0f / FRAME_LEN);
            const float mB  = (msum[g][1] + msum[g][3]) * (32768.0f / FRAME_LEN);
            const float mcA = mA * (1.0f - PREEMPH);
            const float mcB = mB * (1.0f - PREEMPH);
            #pragma unroll
            for (int r = 0; r < 7; ++r) {
                float vA = (a[r]  - PREEMPH * pa[r]) * 32768.0f - mcA;
                float vB = (bb[r] - PREEMPH * pb[r]) * 32768.0f - mcB;
                if (j == 0 && r == 0) {
                    vA = (a[0]  * 32768.0f - mA) * (1.0f - PREEMPH);
                    vB = (bb[0] * 32768.0f - mB) * (1.0f - PREEMPH);
                }
                vr[r] = vA * win_r[r];
                vi[r] = vB * win_r[r];
            }
            vr[7] = 0.0f; vi[7] = 0.0f;
        }

        // ---- pass 1 (Ns=1) directly from registers -> B
        fft8(vr, vi);
        {
            const int d = j << 3;
            #pragma unroll
            for (int m = 0; m < 8; ++m)
                B[g][PHYS8(d + BRv[m])] = make_float2(vr[m], vi[m]);
        }
        GBAR();

        // ---- pass 2: B -> A  (Ns=8); progressive register twiddles
        {
            float wr = 1.0f, wi = 0.0f;
            #pragma unroll
            for (int r = 0; r < 8; ++r) {
                float2 z = B[g][PHYS8(j + (r << 6))];
                vr[r] = z.x; vi[r] = z.y;
                if (r) {
                    CMUL(wr, wi, b2.x, b2.y);
                    CMUL(vr[r], vi[r], wr, wi);
                }
            }
            fft8(vr, vi);
            const int d = ((j >> 3) << 6) + (j & 7);
            #pragma unroll
            for (int m = 0; m < 8; ++m)
                A[g][PHYS8(d + (BRv[m] << 3))] = make_float2(vr[m], vi[m]);
        }
        GBAR();

        // ---- pass 3: A -> B  (Ns=64); progressive twiddles
        {
            float wr = 1.0f, wi = 0.0f;
            #pragma unroll
            for (int r = 0; r < 8; ++r) {
                float2 z = A[g][PHYS8(j + (r << 6))];
                vr[r] = z.x; vi[r] = z.y;
                if (r) {
                    CMUL(wr, wi, b3.x, b3.y);
                    CMUL(vr[r], vi[r], wr, wi);
                }
            }
            fft8(vr, vi);
            #pragma unroll
            for (int m = 0; m < 8; ++m)
                B[g][PHYS8(j + (BRv[m] << 6))] = make_float2(vr[m], vi[m]);
        }
        GBAR();

        // ---- unpack B -> power spectra into specg (A bytes); Z = A + iB
        for (int k = j; k < NBINS; k += 64) {
            const int mm = (FFT_LEN - k) & (FFT_LEN - 1);
            float2 z1 = B[g][PHYS8(k)];
            float2 z2 = B[g][PHYS8(mm)];
            float ar = z1.x + z2.x, ai = z1.y - z2.y;
            float br = z1.y + z2.y, bi = z1.x - z2.x;
            specg[k]           = 0.25f * (ar * ar + ai * ai);
            specg[SPEC_LD + k] = 0.25f * (br * br + bi * bi);
        }
        GBAR();

        // ---- mel + log + stats: one task = one bin x BOTH frames
        //      (weights loaded once, dotted against both spec rows)
        #pragma unroll
        for (int slot = 0; slot < 2; ++slot) {
            const int b = j + slot * 64;
            if (b < NMEL) {
                const int lo = klo_s[b], ww = wid_s[b], off = off_s[b];
                float accA = 0.0f, accB = 0.0f;
                int i = 0;
                if ((lo & 1) && ww > 0) {        // scalar prologue to even k
                    float w0 = wts_s[off];
                    accA = fmaf(specg[lo], w0, accA);
                    accB = fmaf(specg[SPEC_LD + lo], w0, accB);
                    i = 1;
                }
                const float2* spA = (const float2*)(specg + lo + i);
                const float2* spB = (const float2*)(specg + SPEC_LD + lo + i);
                const float2* wt2 = (const float2*)(wts_s + off + i);
                const int n2 = (ww - i) >> 1;
                for (int u = 0; u < n2; ++u) {
                    float2 w2 = wt2[u];
                    float2 sA = spA[u];
                    float2 sB = spB[u];
                    accA = fmaf(sA.x, w2.x, accA);
                    accA = fmaf(sA.y, w2.y, accA);
                    accB = fmaf(sB.x, w2.x, accB);
                    accB = fmaf(sB.y, w2.y, accB);
                }
                if ((ww - i) & 1) {              // scalar tail
                    float wt = wts_s[off + ww - 1];
                    accA = fmaf(specg[lo + ww - 1], wt, accA);
                    accB = fmaf(specg[SPEC_LD + lo + ww - 1], wt, accB);
                }
                float lvA = 0.0f, lvB = 0.0f;
                if (fg < num_frames) {
                    lvA = logf(fmaxf(accA, MEL_FLOOR));
                    g_mel[(long long)fg * NMEL + b] = lvA;
                }
                if (fg + 1 < num_frames) {
                    lvB = logf(fmaxf(accB, MEL_FLOOR));
                    g_mel[(long long)(fg + 1) * NMEL + b] = lvB;
                }
                acc_s[slot] += lvA + lvB;
                acc_q[slot] += lvA * lvA + lvB * lvB;
            }
        }
        // no end barrier: next iteration's mean-exchange GBAR provides the ordering
    }

    #pragma unroll
    for (int slot = 0; slot < 2; ++slot) {
        int a = blockIdx.x * PB + g * 128 + slot * 64 + j;
        g_psum[a] = acc_s[slot];
        g_psq [a] = acc_q[slot];
    }
}

// ---------------------------------------------------------------------------
// One block per mel bin; per (block i, group g) one partial: a = i*PB + g*128 + b
__global__ void reduce2_kernel(int num_frames) {
    __shared__ double sh_s[256], sh_q[256];
    const int b = blockIdx.x;
    const int t = threadIdx.x;
    double s = 0.0, q = 0.0;
    for (int p = t; p < ABLOCKS * 4; p += 256) {
        int i  = p >> 2;
        int gg = p & 3;
        int a  = i * PB + gg * 128 + b;
        s += (double)g_psum[a];
        q += (double)g_psq [a];
    }
    sh_s[t] = s; sh_q[t] = q;
    __syncthreads();
    #pragma unroll
    for (int o = 128; o > 0; o >>= 1) {
        if (t < o) { sh_s[t] += sh_s[t + o]; sh_q[t] += sh_q[t + o]; }
        __syncthreads();
    }
    if (t == 0) {
        double F = (double)num_frames;
        double mean = sh_s[0] / F;
        double var  = (sh_q[0] - F * mean * mean) / (F - 1.0);
        if (var < 0.0) var = 0.0;
        g_mean[b] = (float)mean;
        g_istd[b] = (float)(1.0 / sqrt(var + 1e-7));
    }
}

// ---------------------------------------------------------------------------
__global__ void normalize_kernel(float4* __restrict__ out, int n4) {
    __shared__ float mean_s[NMEL], istd_s[NMEL];
    if (threadIdx.x < NMEL) {
        mean_s[threadIdx.x] = g_mean[threadIdx.x];
        istd_s[threadIdx.x] = g_istd[threadIdx.x];
    }
    __syncthreads();
    const float4* mel4 = (const float4*)g_mel;
    const int stride = gridDim.x * blockDim.x;
    for (int i = blockIdx.x * blockDim.x + threadIdx.x; i < n4; i += 2 * stride) {
        const int i2 = i + stride;
        float4 v1 = mel4[i];
        float4 v2;
        const bool p2ok = (i2 < n4);
        if (p2ok) v2 = mel4[i2];
        int b1 = (i % 20) * 4;
        float4 r1;
        r1.x = (v1.x - mean_s[b1    ]) * istd_s[b1    ];
        r1.y = (v1.y - mean_s[b1 + 1]) * istd_s[b1 + 1];
        r1.z = (v1.z - mean_s[b1 + 2]) * istd_s[b1 + 2];
        r1.w = (v1.w - mean_s[b1 + 3]) * istd_s[b1 + 3];
        out[i] = r1;
        if (p2ok) {
            int b2 = (i2 % 20) * 4;
            float4 r2;
            r2.x = (v2.x - mean_s[b2    ]) * istd_s[b2    ];
            r2.y = (v2.y - mean_s[b2 + 1]) * istd_s[b2 + 1];
            r2.z = (v2.z - mean_s[b2 + 2]) * istd_s[b2 + 2];
            r2.w = (v2.w - mean_s[b2 + 3]) * istd_s[b2 + 3];
            out[i2] = r2;
        }
    }
}

// ---------------------------------------------------------------------------
extern "C" void kernel_launch(void* const* d_in, const int* in_sizes, int n_in,
                              void* d_out, int out_size) {
    const float* wav = (const float*)d_in[0];
    const float* fb  = (const float*)d_in[1];
    const float* win = (const float*)d_in[2];
    float* out = (float*)d_out;

    int T = in_sizes[0];
    int F = 1 + (T - FRAME_LEN) / HOP;
    if (F > MAX_FRAMES) F = MAX_FRAMES;

    const int dynB = 2 * 4 * BUF * 8;   // A + B float2[4][BUF] = 36864 B

    static int attr_set = 0;
    if (!attr_set) {
        cudaFuncSetAttribute(fused_kernel,
                             cudaFuncAttributePreferredSharedMemoryCarveout, 100);
        attr_set = 1;
    }

    init_kernel<<<1, 640>>>(fb);
    fused_kernel<<<ABLOCKS, 256, dynB>>>(wav, win, F, T);
    reduce2_kernel<<<NMEL, 256>>>(F);
    normalize_kernel<<<2048, 256>>>((float4*)out, F * NMEL / 4);
}